// round 5
// baseline (speedup 1.0000x reference)
#include <cuda_runtime.h>
#include <cuda_bf16.h>
#include <cstdint>

// Problem constants (fixed by setup_inputs)
#define BATCH 16
#define HH 56
#define WW_ 56
#define CC 1024
#define KK 150
#define WS 7
#define L_TOK (HH*WW_)            // 3136
#define NTOK (BATCH*L_TOK)        // 50176 token rows (also window-layout rows)
#define NWIN (NTOK/49)            // 1024 windows

// ---------------- device scratch (static globals; no runtime alloc) -------------
__device__ float sc_win[50176ull*1024];     // LN output, window-contiguous [w*49+t][C]
__device__ float sc_map[50176ull*150];      // seg_map  [row][K]
__device__ float sc_ft [50176ull*150];      // seg_ft   [row][K]
__device__ float sc_v  [50176ull*1024];     // feats(V) [row][C]
__device__ float sc_at [50176ull*1024];     // attn out [row][C]

// ---------------- helpers -------------------------------------------------------
__device__ __forceinline__ float f2tf32(float x) {
    // round-to-nearest tf32 (keep as fp32 bit pattern with low mantissa zeroed)
    unsigned u;
    asm("cvt.rna.tf32.f32 %0, %1;" : "=r"(u) : "f"(x));
    return __uint_as_float(u);
}

__device__ __forceinline__ void mma_tf32(float (&c)[4], const unsigned (&a)[4],
                                         const unsigned (&b)[2]) {
    asm volatile(
        "mma.sync.aligned.m16n8k8.row.col.f32.tf32.tf32.f32 "
        "{%0,%1,%2,%3}, {%4,%5,%6,%7}, {%8,%9}, {%0,%1,%2,%3};\n"
        : "+f"(c[0]), "+f"(c[1]), "+f"(c[2]), "+f"(c[3])
        : "r"(a[0]), "r"(a[1]), "r"(a[2]), "r"(a[3]), "r"(b[0]), "r"(b[1]));
}

// row in window layout -> token index (b*3136 + l) in image layout
__device__ __forceinline__ int row_to_token(int rr) {
    int wI = rr / 49;
    int tI = rr - wI * 49;
    int b  = wI >> 6;          // 64 windows per batch
    int wl = wI & 63;
    int i  = tI / 7;
    int j  = tI - i * 7;
    int gr = (wl >> 3) * 7 + i;
    int gc = (wl & 7) * 7 + j;
    return b * L_TOK + gr * WW_ + gc;
}

// ---------------- LayerNorm + window partition ---------------------------------
__global__ void __launch_bounds__(256) ln_win_kernel(
    const float* __restrict__ x, const float* __restrict__ nw,
    const float* __restrict__ nb, float* __restrict__ win)
{
    const int token = blockIdx.x;          // 0..50175  (= b*3136 + l)
    const int tid   = threadIdx.x;
    const int b   = token / L_TOK;
    const int l   = token - b * L_TOK;
    const int row = l / WW_;
    const int col = l - row * WW_;
    const int w   = b * 64 + (row / 7) * 8 + (col / 7);
    const int t   = (row % 7) * 7 + (col % 7);

    const float4* xp = reinterpret_cast<const float4*>(x + (size_t)token * CC);
    float4 v = xp[tid];
    float s  = v.x + v.y + v.z + v.w;
    float s2 = v.x*v.x + v.y*v.y + v.z*v.z + v.w*v.w;

    // warp reduce
    #pragma unroll
    for (int off = 16; off > 0; off >>= 1) {
        s  += __shfl_xor_sync(0xffffffff, s,  off);
        s2 += __shfl_xor_sync(0xffffffff, s2, off);
    }
    __shared__ float red0[8], red1[8];
    __shared__ float s_mu, s_rs;
    const int warp = tid >> 5, lane = tid & 31;
    if (lane == 0) { red0[warp] = s; red1[warp] = s2; }
    __syncthreads();
    if (tid == 0) {
        float t0 = 0.f, t1 = 0.f;
        #pragma unroll
        for (int i = 0; i < 8; i++) { t0 += red0[i]; t1 += red1[i]; }
        float mu  = t0 * (1.0f / CC);
        float var = t1 * (1.0f / CC) - mu * mu;
        s_mu = mu;
        s_rs = rsqrtf(var + 1e-5f);
    }
    __syncthreads();
    const float mu = s_mu, rs = s_rs;

    float4 w4 = reinterpret_cast<const float4*>(nw)[tid];
    float4 b4 = reinterpret_cast<const float4*>(nb)[tid];
    float4 o;
    o.x = (v.x - mu) * rs * w4.x + b4.x;
    o.y = (v.y - mu) * rs * w4.y + b4.y;
    o.z = (v.z - mu) * rs * w4.z + b4.z;
    o.w = (v.w - mu) * rs * w4.w + b4.w;
    reinterpret_cast<float4*>(win + (size_t)(w * 49 + t) * CC)[tid] = o;
}

// ---------------- TF32 GEMM: C[M,N] = A[M,1024] @ W[N,1024]^T + bias -----------
// EPI 0: Cout[rr*N + col] = v
// EPI 1: Cout[rr*150 + col] = v; out2[token*150 + col] = v      (Q/sem)
// EPI 2: out2[token*1024 + col] = gamma*v + resid[rr*1024+col]  (R + residual)
template <int EPI>
__global__ void __launch_bounds__(256) gemm_tf32_kernel(
    const float* __restrict__ A, const float* __restrict__ Wt,
    const float* __restrict__ bias, float* __restrict__ Cout, int N,
    float* __restrict__ out2, const float* __restrict__ resid,
    const float* __restrict__ gammap)
{
    __shared__ __align__(16) float As[128][36];
    __shared__ __align__(16) float Bs[128][36];

    const int tid  = threadIdx.x;
    const int warp = tid >> 5, lane = tid & 31;
    const int wm   = warp >> 2, wn = warp & 3;       // 2 x 4 warp grid
    const int grp  = lane >> 2, tid4 = lane & 3;
    const int blockN = blockIdx.x * 128;
    const int blockM = blockIdx.y * 128;

    float acc[4][4][4];
    #pragma unroll
    for (int a = 0; a < 4; a++)
        #pragma unroll
        for (int b = 0; b < 4; b++)
            #pragma unroll
            for (int c = 0; c < 4; c++) acc[a][b][c] = 0.f;

    float4 ra[4], rb[4];

    auto load_tiles = [&](int kt) {
        const int k0 = kt * 32;
        #pragma unroll
        for (int i = 0; i < 4; i++) {
            int q  = i * 256 + tid;
            int rr = q >> 3, cc = q & 7;
            ra[i] = *reinterpret_cast<const float4*>(
                A + (size_t)(blockM + rr) * 1024 + k0 + cc * 4);
            int rw = blockN + rr;
            if (rw < N) {
                rb[i] = *reinterpret_cast<const float4*>(
                    Wt + (size_t)rw * 1024 + k0 + cc * 4);
            } else {
                rb[i] = make_float4(0.f, 0.f, 0.f, 0.f);
            }
        }
    };

    auto store_tiles = [&]() {
        #pragma unroll
        for (int i = 0; i < 4; i++) {
            int q  = i * 256 + tid;
            int rr = q >> 3, cc = q & 7;
            float4 av = ra[i], bv = rb[i];
            float4 ac = make_float4(f2tf32(av.x), f2tf32(av.y), f2tf32(av.z), f2tf32(av.w));
            float4 bc = make_float4(f2tf32(bv.x), f2tf32(bv.y), f2tf32(bv.z), f2tf32(bv.w));
            *reinterpret_cast<float4*>(&As[rr][cc * 4]) = ac;
            *reinterpret_cast<float4*>(&Bs[rr][cc * 4]) = bc;
        }
    };

    load_tiles(0);

    for (int kt = 0; kt < 32; kt++) {
        if (kt) __syncthreads();
        store_tiles();
        __syncthreads();
        if (kt + 1 < 32) load_tiles(kt + 1);

        #pragma unroll
        for (int ks = 0; ks < 4; ks++) {
            const int k = ks * 8;
            unsigned a[4][4], b[4][2];
            #pragma unroll
            for (int mt = 0; mt < 4; mt++) {
                int r = wm * 64 + mt * 16 + grp;
                a[mt][0] = __float_as_uint(As[r][k + tid4]);
                a[mt][1] = __float_as_uint(As[r + 8][k + tid4]);
                a[mt][2] = __float_as_uint(As[r][k + tid4 + 4]);
                a[mt][3] = __float_as_uint(As[r + 8][k + tid4 + 4]);
            }
            #pragma unroll
            for (int nt = 0; nt < 4; nt++) {
                int cn = wn * 32 + nt * 8 + grp;
                b[nt][0] = __float_as_uint(Bs[cn][k + tid4]);
                b[nt][1] = __float_as_uint(Bs[cn][k + tid4 + 4]);
            }
            #pragma unroll
            for (int mt = 0; mt < 4; mt++)
                #pragma unroll
                for (int nt = 0; nt < 4; nt++)
                    mma_tf32(acc[mt][nt], a[mt], b[nt]);
        }
    }

    // -------- epilogue --------
    float gm = 0.f;
    if (EPI == 2) gm = __ldg(gammap);

    #pragma unroll
    for (int mt = 0; mt < 4; mt++) {
        int rbase = blockM + wm * 64 + mt * 16 + grp;
        #pragma unroll
        for (int half = 0; half < 2; half++) {
            int rr = rbase + half * 8;
            int token = 0;
            if (EPI != 0) token = row_to_token(rr);
            #pragma unroll
            for (int nt = 0; nt < 4; nt++) {
                #pragma unroll
                for (int cc = 0; cc < 2; cc++) {
                    int col = blockN + wn * 32 + nt * 8 + tid4 * 2 + cc;
                    if (col < N) {
                        float v = acc[mt][nt][half * 2 + cc] + bias[col];
                        if (EPI == 0) {
                            Cout[(size_t)rr * N + col] = v;
                        } else if (EPI == 1) {
                            Cout[(size_t)rr * 150 + col] = v;
                            out2[(size_t)token * 150 + col] = v;
                        } else {
                            out2[(size_t)token * 1024 + col] =
                                gm * v + resid[(size_t)rr * 1024 + col];
                        }
                    }
                }
            }
        }
    }
}

// ---------------- per-window attention ------------------------------------------
// S = softmax(seg_map @ seg_ft^T), attn = S @ V    (one block per window)
#define SMAP_OFF 0
#define SFT_OFF  (49*151)
#define SS_OFF   (49*512)          // 25088 floats (after V-chunk region)
#define ATTN_SMEM ((49*512 + 49*49) * 4)   // 109,956 bytes

__global__ void __launch_bounds__(256) attn_kernel(
    const float* __restrict__ segmap, const float* __restrict__ segft,
    const float* __restrict__ featsv, float* __restrict__ attn)
{
    extern __shared__ float sm[];
    float* sMap = sm + SMAP_OFF;    // [49][151]
    float* sFt  = sm + SFT_OFF;     // [49][151]
    float* sS   = sm + SS_OFF;      // [49][49]
    float* sV   = sm;               // [49][512]  (reuses sMap/sFt region in phase 2)

    const int w   = blockIdx.x;
    const int tid = threadIdx.x;

    // phase 1a: stage seg_map / seg_ft
    for (int idx = tid; idx < 49 * 150; idx += 256) {
        int n = idx / 150, k = idx - n * 150;
        sMap[n * 151 + k] = segmap[(size_t)(w * 49 + n) * 150 + k];
        sFt [n * 151 + k] = segft [(size_t)(w * 49 + n) * 150 + k];
    }
    __syncthreads();

    // phase 1b: S = Q K^T
    for (int p = tid; p < 49 * 49; p += 256) {
        int n = p / 49, m = p - n * 49;
        float acc = 0.f;
        const float* qr = sMap + n * 151;
        const float* kr = sFt + m * 151;
        #pragma unroll 5
        for (int k = 0; k < 150; k++) acc += qr[k] * kr[k];
        sS[n * 49 + m] = acc;
    }
    __syncthreads();

    // phase 1c: row softmax (49 rows)
    if (tid < 49) {
        float* row = sS + tid * 49;
        float mx = -1e30f;
        #pragma unroll
        for (int m = 0; m < 49; m++) mx = fmaxf(mx, row[m]);
        float sum = 0.f;
        #pragma unroll
        for (int m = 0; m < 49; m++) {
            float e = __expf(row[m] - mx);
            row[m] = e;
            sum += e;
        }
        float inv = 1.0f / sum;
        #pragma unroll
        for (int m = 0; m < 49; m++) row[m] *= inv;
    }
    __syncthreads();

    // phase 2: attn = S @ V, 512-column chunks of V staged in smem
    for (int chunk = 0; chunk < 2; chunk++) {
        const int c0 = chunk * 512;
        for (int q = tid; q < 49 * 128; q += 256) {
            int m = q / 128, c4 = q - m * 128;
            reinterpret_cast<float4*>(sV)[m * 128 + c4] =
                *reinterpret_cast<const float4*>(
                    featsv + (size_t)(w * 49 + m) * 1024 + c0 + c4 * 4);
        }
        __syncthreads();

        for (int task = tid; task < 49 * 128; task += 256) {
            int n = task / 128, cg = task - n * 128;
            float4 acc = make_float4(0.f, 0.f, 0.f, 0.f);
            const float* srow = sS + n * 49;
            #pragma unroll 7
            for (int m = 0; m < 49; m++) {
                float s = srow[m];
                float4 v = reinterpret_cast<const float4*>(sV)[m * 128 + cg];
                acc.x += s * v.x; acc.y += s * v.y;
                acc.z += s * v.z; acc.w += s * v.w;
            }
            *reinterpret_cast<float4*>(
                attn + (size_t)(w * 49 + n) * 1024 + c0 + cg * 4) = acc;
        }
        __syncthreads();
    }
}

// ---------------- launch --------------------------------------------------------
extern "C" void kernel_launch(void* const* d_in, const int* in_sizes, int n_in,
                              void* d_out, int out_size)
{
    const float* x     = (const float*)d_in[0];
    const float* nw    = (const float*)d_in[1];
    const float* nb    = (const float*)d_in[2];
    const float* wq    = (const float*)d_in[3];
    const float* bq    = (const float*)d_in[4];
    const float* wk    = (const float*)d_in[5];
    const float* bk    = (const float*)d_in[6];
    const float* wv    = (const float*)d_in[7];
    const float* bv    = (const float*)d_in[8];
    const float* wr    = (const float*)d_in[9];
    const float* br    = (const float*)d_in[10];
    const float* gamma = (const float*)d_in[11];

    float* out     = (float*)d_out;
    float* sem_out = out;                                    // (B,L,K) first
    float* x_out   = out + (size_t)NTOK * KK;                // then (B,L,C)

    float *p_win, *p_map, *p_ft, *p_v, *p_at;
    cudaGetSymbolAddress((void**)&p_win, sc_win);
    cudaGetSymbolAddress((void**)&p_map, sc_map);
    cudaGetSymbolAddress((void**)&p_ft,  sc_ft);
    cudaGetSymbolAddress((void**)&p_v,   sc_v);
    cudaGetSymbolAddress((void**)&p_at,  sc_at);

    // 1) LayerNorm + window partition
    ln_win_kernel<<<NTOK, 256>>>(x, nw, nb, p_win);

    // 2) seg_map = win @ wq^T + bq  (scratch + sem output, window-reversed)
    gemm_tf32_kernel<1><<<dim3(2, 392), 256>>>(p_win, wq, bq, p_map, 150,
                                               sem_out, nullptr, nullptr);
    // 3) seg_ft = win @ wk^T + bk
    gemm_tf32_kernel<0><<<dim3(2, 392), 256>>>(p_win, wk, bk, p_ft, 150,
                                               nullptr, nullptr, nullptr);
    // 4) feats = win @ wv^T + bv
    gemm_tf32_kernel<0><<<dim3(8, 392), 256>>>(p_win, wv, bv, p_v, 1024,
                                               nullptr, nullptr, nullptr);
    // 5) per-window softmax attention
    cudaFuncSetAttribute(attn_kernel, cudaFuncAttributeMaxDynamicSharedMemorySize,
                         ATTN_SMEM);
    attn_kernel<<<NWIN, 256, ATTN_SMEM>>>(p_map, p_ft, p_v, p_at);

    // 6) x_out = gamma*(attn @ wr^T + br) + win   (window-reversed scatter)
    gemm_tf32_kernel<2><<<dim3(8, 392), 256>>>(p_at, wr, br, nullptr, 1024,
                                               x_out, p_win, gamma);
}

// round 7
// speedup vs baseline: 1.0283x; 1.0283x over previous
#include <cuda_runtime.h>
#include <cuda_bf16.h>
#include <cstdint>

// Problem constants (fixed by setup_inputs)
#define BATCH 16
#define HH 56
#define WW_ 56
#define CC 1024
#define KK 150
#define WS 7
#define L_TOK (HH*WW_)            // 3136
#define NTOK (BATCH*L_TOK)        // 50176 token rows (window-layout rows)
#define NWIN (NTOK/49)            // 1024 windows

// ---------------- device scratch (static globals; no runtime alloc) -------------
__device__ float sc_win [50176ull*1024];    // LN output fp32 (residual), logical ch
__device__ float sc_wint[50176ull*1024];    // LN output tf32-rounded, K-PERMUTED
__device__ float sc_map [50176ull*150];     // seg_map  [row][K]
__device__ float sc_ft  [50176ull*150];     // seg_ft   [row][K]
__device__ float sc_v   [50176ull*1024];    // feats(V), channels PERMUTED
__device__ float sc_at  [50176ull*1024];    // attn out tf32-rounded, PERMUTED ch
__device__ float sc_wvr [1024ull*1024];     // wv rounded + K-permuted
__device__ float sc_wrr [1024ull*1024];     // wr rounded + K-permuted
__device__ float sc_wqk [384ull*1024];      // [wq;wk;zeros] rounded + K-permuted

// ---------------- helpers -------------------------------------------------------
__device__ __forceinline__ float f2tf32(float x) {
    unsigned u;
    asm("cvt.rna.tf32.f32 %0, %1;" : "=r"(u) : "f"(x));
    return __uint_as_float(u);
}

// fragment-friendly K permutation, within each 32-column (=128B) block
__device__ __forceinline__ int permk(int c) {
    return (c & ~31) + ((c & 3) << 3) + (((c >> 3) & 3) << 1) + ((c >> 2) & 1);
}

__device__ __forceinline__ void mma_tf32(float (&c)[4], const unsigned (&a)[4],
                                         const unsigned (&b)[2]) {
    asm volatile(
        "mma.sync.aligned.m16n8k8.row.col.f32.tf32.tf32.f32 "
        "{%0,%1,%2,%3}, {%4,%5,%6,%7}, {%8,%9}, {%0,%1,%2,%3};\n"
        : "+f"(c[0]), "+f"(c[1]), "+f"(c[2]), "+f"(c[3])
        : "r"(a[0]), "r"(a[1]), "r"(a[2]), "r"(a[3]), "r"(b[0]), "r"(b[1]));
}

__device__ __forceinline__ uint32_t smem_u32(const void* p) {
    uint32_t a;
    asm("{ .reg .u64 t; cvta.to.shared.u64 t, %1; cvt.u32.u64 %0, t; }"
        : "=r"(a) : "l"(p));
    return a;
}

// row in window layout -> token index (b*3136 + l) in image layout
__device__ __forceinline__ int row_to_token(int rr) {
    int wI = rr / 49;
    int tI = rr - wI * 49;
    int b  = wI >> 6;
    int wl = wI & 63;
    int i  = tI / 7;
    int j  = tI - i * 7;
    int gr = (wl >> 3) * 7 + i;
    int gc = (wl & 7) * 7 + j;
    return b * L_TOK + gr * WW_ + gc;
}

// ---------------- weight prep: round to tf32 + K-permute ------------------------
__global__ void __launch_bounds__(256) prep_weights_kernel(
    const float* __restrict__ wq, const float* __restrict__ wk,
    const float* __restrict__ wv, const float* __restrict__ wr,
    float* __restrict__ owqk, float* __restrict__ owv, float* __restrict__ owr)
{
    int t = blockIdx.x * 256 + threadIdx.x;       // 0..262143
    {   // wv, wr: 1024x1024 = 262144 float4 tasks
        int row = t >> 8;
        int k0  = (t & 255) * 4;
        size_t base = (size_t)row * 1024;
        float4 v = *reinterpret_cast<const float4*>(wv + base + k0);
        owv[base + permk(k0 + 0)] = f2tf32(v.x);
        owv[base + permk(k0 + 1)] = f2tf32(v.y);
        owv[base + permk(k0 + 2)] = f2tf32(v.z);
        owv[base + permk(k0 + 3)] = f2tf32(v.w);
        float4 w = *reinterpret_cast<const float4*>(wr + base + k0);
        owr[base + permk(k0 + 0)] = f2tf32(w.x);
        owr[base + permk(k0 + 1)] = f2tf32(w.y);
        owr[base + permk(k0 + 2)] = f2tf32(w.z);
        owr[base + permk(k0 + 3)] = f2tf32(w.w);
    }
    if (t < 384 * 256) {   // packed [wq;wk;zeros]: 384 rows
        int row = t >> 8;
        int k0  = (t & 255) * 4;
        float4 v = make_float4(0.f, 0.f, 0.f, 0.f);
        if (row < 150)
            v = *reinterpret_cast<const float4*>(wq + (size_t)row * 1024 + k0);
        else if (row < 300)
            v = *reinterpret_cast<const float4*>(wk + (size_t)(row - 150) * 1024 + k0);
        size_t base = (size_t)row * 1024;
        owqk[base + permk(k0 + 0)] = f2tf32(v.x);
        owqk[base + permk(k0 + 1)] = f2tf32(v.y);
        owqk[base + permk(k0 + 2)] = f2tf32(v.z);
        owqk[base + permk(k0 + 3)] = f2tf32(v.w);
    }
}

// ---------------- LayerNorm + window partition ----------------------------------
// writes: win (fp32 logical) and wint (tf32-rounded, K-permuted)
__global__ void __launch_bounds__(256) ln_win_kernel(
    const float* __restrict__ x, const float* __restrict__ nw,
    const float* __restrict__ nb, float* __restrict__ win,
    float* __restrict__ winr)
{
    const int token = blockIdx.x;
    const int tid   = threadIdx.x;
    const int b   = token / L_TOK;
    const int l   = token - b * L_TOK;
    const int row = l / WW_;
    const int col = l - row * WW_;
    const int w   = b * 64 + (row / 7) * 8 + (col / 7);
    const int t   = (row % 7) * 7 + (col % 7);

    const float4* xp = reinterpret_cast<const float4*>(x + (size_t)token * CC);
    float4 v = xp[tid];
    float s  = v.x + v.y + v.z + v.w;
    float s2 = v.x*v.x + v.y*v.y + v.z*v.z + v.w*v.w;

    #pragma unroll
    for (int off = 16; off > 0; off >>= 1) {
        s  += __shfl_xor_sync(0xffffffff, s,  off);
        s2 += __shfl_xor_sync(0xffffffff, s2, off);
    }
    __shared__ float red0[8], red1[8];
    __shared__ float s_mu, s_rs;
    const int warp = tid >> 5, lane = tid & 31;
    if (lane == 0) { red0[warp] = s; red1[warp] = s2; }
    __syncthreads();
    if (tid == 0) {
        float t0 = 0.f, t1 = 0.f;
        #pragma unroll
        for (int i = 0; i < 8; i++) { t0 += red0[i]; t1 += red1[i]; }
        float mu  = t0 * (1.0f / CC);
        float var = t1 * (1.0f / CC) - mu * mu;
        s_mu = mu;
        s_rs = rsqrtf(var + 1e-5f);
    }
    __syncthreads();
    const float mu = s_mu, rs = s_rs;

    float4 w4 = reinterpret_cast<const float4*>(nw)[tid];
    float4 b4 = reinterpret_cast<const float4*>(nb)[tid];
    float4 o;
    o.x = (v.x - mu) * rs * w4.x + b4.x;
    o.y = (v.y - mu) * rs * w4.y + b4.y;
    o.z = (v.z - mu) * rs * w4.z + b4.z;
    o.w = (v.w - mu) * rs * w4.w + b4.w;
    const size_t dst = (size_t)(w * 49 + t) * CC;
    reinterpret_cast<float4*>(win + dst)[tid] = o;
    const int c0 = tid * 4;
    winr[dst + permk(c0 + 0)] = f2tf32(o.x);
    winr[dst + permk(c0 + 1)] = f2tf32(o.y);
    winr[dst + permk(c0 + 2)] = f2tf32(o.z);
    winr[dst + permk(c0 + 3)] = f2tf32(o.w);
}

// ---------------- TF32 GEMM with cp.async pipeline + permuted fragments ---------
// C[M,N] = A[M,1024] @ B[N,1024]^T ;  A,B pre-rounded to tf32 and K-permuted.
// EPI 0 (V):  out0[rr*1024 + permk(col)] = v + bias[col]
// EPI 1 (R):  out0[token*1024 + col]     = gamma*(v + bias[col]) + resid[rr*1024+col]
// EPI 2 (QK): col<150  -> v+bias[col]      -> out0[rr*150+col], out1[token*150+col]
//             col<300  -> v+bias2[col-150] -> out2[rr*150+col-150]
#define NS 3
#define STG_F (128*36)
#define STAGE_F (2*STG_F)
#define GEMM_SMEM (NS*STAGE_F*4)      // 110592 bytes

template <int EPI>
__global__ void __launch_bounds__(256, 2) gemm_cp_kernel(
    const float* __restrict__ A, const float* __restrict__ B,
    const float* __restrict__ bias, const float* __restrict__ bias2,
    float* __restrict__ out0, float* __restrict__ out1, float* __restrict__ out2,
    const float* __restrict__ resid, const float* __restrict__ gammap)
{
    extern __shared__ float sm[];
    const int tid  = threadIdx.x;
    const int warp = tid >> 5, lane = tid & 31;
    const int wm   = warp >> 2, wn = warp & 3;      // 2x4 warp grid, 64x32 tiles
    const int grp  = lane >> 2, tid4 = lane & 3;
    const int blockN = blockIdx.x * 128;
    const int blockM = blockIdx.y * 128;
    const uint32_t sbase = smem_u32(sm);

    float acc[4][4][4];
    #pragma unroll
    for (int a = 0; a < 4; a++)
        #pragma unroll
        for (int b = 0; b < 4; b++)
            #pragma unroll
            for (int c = 0; c < 4; c++) acc[a][b][c] = 0.f;

    auto issue = [&](int kt) {
        if (kt < 32) {
            const int s  = kt - (kt / NS) * NS;
            const int k0 = kt * 32;
            const uint32_t ab = sbase + (uint32_t)s * (STAGE_F * 4);
            #pragma unroll
            for (int i = 0; i < 4; i++) {
                int idx = i * 256 + tid;           // 0..1023
                int row = idx >> 3, ch = idx & 7;
                uint32_t off = (uint32_t)(row * 36 + ch * 4) * 4;
                const float* sa = A + (size_t)(blockM + row) * 1024 + k0 + ch * 4;
                asm volatile("cp.async.cg.shared.global [%0], [%1], 16;\n"
                             :: "r"(ab + off), "l"(sa));
                const float* sb = B + (size_t)(blockN + row) * 1024 + k0 + ch * 4;
                asm volatile("cp.async.cg.shared.global [%0], [%1], 16;\n"
                             :: "r"(ab + STG_F * 4 + off), "l"(sb));
            }
        }
        asm volatile("cp.async.commit_group;\n" ::: "memory");
    };

    issue(0);
    issue(1);

    for (int kt = 0; kt < 32; kt++) {
        asm volatile("cp.async.wait_group 1;\n" ::: "memory");
        __syncthreads();
        issue(kt + 2);

        const float* As = sm + (kt - (kt / NS) * NS) * STAGE_F;
        const float* Bs = As + STG_F;

        #pragma unroll
        for (int kp = 0; kp < 2; kp++) {
            float4 bf[4];
            #pragma unroll
            for (int nt = 0; nt < 4; nt++)
                bf[nt] = *reinterpret_cast<const float4*>(
                    &Bs[(wn * 32 + nt * 8 + grp) * 36 + tid4 * 8 + kp * 4]);
            #pragma unroll
            for (int mt = 0; mt < 4; mt++) {
                const int r = wm * 64 + mt * 16 + grp;
                float4 a0 = *reinterpret_cast<const float4*>(
                    &As[r * 36 + tid4 * 8 + kp * 4]);
                float4 a1 = *reinterpret_cast<const float4*>(
                    &As[(r + 8) * 36 + tid4 * 8 + kp * 4]);
                unsigned af0[4] = {__float_as_uint(a0.x), __float_as_uint(a1.x),
                                   __float_as_uint(a0.y), __float_as_uint(a1.y)};
                unsigned af1[4] = {__float_as_uint(a0.z), __float_as_uint(a1.z),
                                   __float_as_uint(a0.w), __float_as_uint(a1.w)};
                #pragma unroll
                for (int nt = 0; nt < 4; nt++) {
                    unsigned b0[2] = {__float_as_uint(bf[nt].x),
                                      __float_as_uint(bf[nt].y)};
                    mma_tf32(acc[mt][nt], af0, b0);
                    unsigned b1[2] = {__float_as_uint(bf[nt].z),
                                      __float_as_uint(bf[nt].w)};
                    mma_tf32(acc[mt][nt], af1, b1);
                }
            }
        }
    }

    // -------- epilogue --------
    float gm = 0.f;
    if (EPI == 1) gm = __ldg(gammap);

    #pragma unroll
    for (int mt = 0; mt < 4; mt++) {
        const int rbase = blockM + wm * 64 + mt * 16 + grp;
        #pragma unroll
        for (int half = 0; half < 2; half++) {
            const int rr = rbase + half * 8;
            int token = 0;
            if (EPI != 0) token = row_to_token(rr);
            #pragma unroll
            for (int nt = 0; nt < 4; nt++) {
                #pragma unroll
                for (int cc = 0; cc < 2; cc++) {
                    const int col = blockN + wn * 32 + nt * 8 + tid4 * 2 + cc;
                    const float v = acc[mt][nt][half * 2 + cc];
                    if (EPI == 0) {
                        out0[(size_t)rr * 1024 + permk(col)] = v + bias[col];
                    } else if (EPI == 1) {
                        out0[(size_t)token * 1024 + col] =
                            gm * (v + bias[col]) + resid[(size_t)rr * 1024 + col];
                    } else {
                        if (col < 150) {
                            float o = v + bias[col];
                            out0[(size_t)rr * 150 + col] = o;
                            out1[(size_t)token * 150 + col] = o;
                        } else if (col < 300) {
                            out2[(size_t)rr * 150 + (col - 150)] =
                                v + bias2[col - 150];
                        }
                    }
                }
            }
        }
    }
}

// ---------------- per-window attention ------------------------------------------
// channels of featsv/attn are permuted labels; attention is channel-independent.
#define SMAP_OFF 0
#define SFT_OFF  (49*151)
#define SS_OFF   (49*512)
#define ATTN_SMEM ((49*512 + 49*49) * 4)

__global__ void __launch_bounds__(256) attn_kernel(
    const float* __restrict__ segmap, const float* __restrict__ segft,
    const float* __restrict__ featsv, float* __restrict__ attn)
{
    extern __shared__ float sm[];
    float* sMap = sm + SMAP_OFF;
    float* sFt  = sm + SFT_OFF;
    float* sS   = sm + SS_OFF;
    float* sV   = sm;

    const int w   = blockIdx.x;
    const int tid = threadIdx.x;

    for (int idx = tid; idx < 49 * 150; idx += 256) {
        int n = idx / 150, k = idx - n * 150;
        sMap[n * 151 + k] = segmap[(size_t)(w * 49 + n) * 150 + k];
        sFt [n * 151 + k] = segft [(size_t)(w * 49 + n) * 150 + k];
    }
    __syncthreads();

    for (int p = tid; p < 49 * 49; p += 256) {
        int n = p / 49, m = p - n * 49;
        float acc = 0.f;
        const float* qr = sMap + n * 151;
        const float* kr = sFt + m * 151;
        #pragma unroll 5
        for (int k = 0; k < 150; k++) acc += qr[k] * kr[k];
        sS[n * 49 + m] = acc;
    }
    __syncthreads();

    if (tid < 49) {
        float* row = sS + tid * 49;
        float mx = -1e30f;
        #pragma unroll
        for (int m = 0; m < 49; m++) mx = fmaxf(mx, row[m]);
        float sum = 0.f;
        #pragma unroll
        for (int m = 0; m < 49; m++) {
            float e = __expf(row[m] - mx);
            row[m] = e;
            sum += e;
        }
        float inv = 1.0f / sum;
        #pragma unroll
        for (int m = 0; m < 49; m++) row[m] *= inv;
    }
    __syncthreads();

    for (int chunk = 0; chunk < 2; chunk++) {
        const int c0 = chunk * 512;
        for (int q = tid; q < 49 * 128; q += 256) {
            int m = q / 128, c4 = q - m * 128;
            reinterpret_cast<float4*>(sV)[m * 128 + c4] =
                *reinterpret_cast<const float4*>(
                    featsv + (size_t)(w * 49 + m) * 1024 + c0 + c4 * 4);
        }
        __syncthreads();

        for (int task = tid; task < 49 * 128; task += 256) {
            int n = task / 128, cg = task - n * 128;
            float4 acc = make_float4(0.f, 0.f, 0.f, 0.f);
            const float* srow = sS + n * 49;
            #pragma unroll 7
            for (int m = 0; m < 49; m++) {
                float s = srow[m];
                float4 v = reinterpret_cast<const float4*>(sV)[m * 128 + cg];
                acc.x += s * v.x; acc.y += s * v.y;
                acc.z += s * v.z; acc.w += s * v.w;
            }
            // tf32-round at store: this buffer is only ever an MMA A-operand
            float4 o = make_float4(f2tf32(acc.x), f2tf32(acc.y),
                                   f2tf32(acc.z), f2tf32(acc.w));
            *reinterpret_cast<float4*>(
                attn + (size_t)(w * 49 + n) * 1024 + c0 + cg * 4) = o;
        }
        __syncthreads();
    }
}

// ---------------- launch --------------------------------------------------------
extern "C" void kernel_launch(void* const* d_in, const int* in_sizes, int n_in,
                              void* d_out, int out_size)
{
    const float* x     = (const float*)d_in[0];
    const float* nw    = (const float*)d_in[1];
    const float* nb    = (const float*)d_in[2];
    const float* wq    = (const float*)d_in[3];
    const float* bq    = (const float*)d_in[4];
    const float* wk    = (const float*)d_in[5];
    const float* bk    = (const float*)d_in[6];
    const float* wv    = (const float*)d_in[7];
    const float* bv    = (const float*)d_in[8];
    const float* wr    = (const float*)d_in[9];
    const float* br    = (const float*)d_in[10];
    const float* gamma = (const float*)d_in[11];

    float* out     = (float*)d_out;
    float* sem_out = out;                                    // (B,L,K) first
    float* x_out   = out + (size_t)NTOK * KK;                // then (B,L,C)

    float *p_win, *p_wint, *p_map, *p_ft, *p_v, *p_at, *p_wvr, *p_wrr, *p_wqk;
    cudaGetSymbolAddress((void**)&p_win,  sc_win);
    cudaGetSymbolAddress((void**)&p_wint, sc_wint);
    cudaGetSymbolAddress((void**)&p_map,  sc_map);
    cudaGetSymbolAddress((void**)&p_ft,   sc_ft);
    cudaGetSymbolAddress((void**)&p_v,    sc_v);
    cudaGetSymbolAddress((void**)&p_at,   sc_at);
    cudaGetSymbolAddress((void**)&p_wvr,  sc_wvr);
    cudaGetSymbolAddress((void**)&p_wrr,  sc_wrr);
    cudaGetSymbolAddress((void**)&p_wqk,  sc_wqk);

    cudaFuncSetAttribute(gemm_cp_kernel<0>,
                         cudaFuncAttributeMaxDynamicSharedMemorySize, GEMM_SMEM);
    cudaFuncSetAttribute(gemm_cp_kernel<1>,
                         cudaFuncAttributeMaxDynamicSharedMemorySize, GEMM_SMEM);
    cudaFuncSetAttribute(gemm_cp_kernel<2>,
                         cudaFuncAttributeMaxDynamicSharedMemorySize, GEMM_SMEM);
    cudaFuncSetAttribute(attn_kernel,
                         cudaFuncAttributeMaxDynamicSharedMemorySize, ATTN_SMEM);

    // 0) round + K-permute weights ([wq;wk] packed, wv, wr)
    prep_weights_kernel<<<1024, 256>>>(wq, wk, wv, wr, p_wqk, p_wvr, p_wrr);

    // 1) LayerNorm + window partition (fp32 residual + tf32-permuted GEMM copy)
    ln_win_kernel<<<NTOK, 256>>>(x, nw, nb, p_win, p_wint);

    // 2) fused Q/K projection: [seg_map | seg_ft] = win @ [wq;wk]^T + [bq;bk]
    gemm_cp_kernel<2><<<dim3(3, 392), 256, GEMM_SMEM>>>(
        p_wint, p_wqk, bq, bk, p_map, sem_out, p_ft, nullptr, nullptr);

    // 3) feats = win @ wv^T + bv  (channels stored permuted)
    gemm_cp_kernel<0><<<dim3(8, 392), 256, GEMM_SMEM>>>(
        p_wint, p_wvr, bv, nullptr, p_v, nullptr, nullptr, nullptr, nullptr);

    // 4) per-window softmax attention
    attn_kernel<<<NWIN, 256, ATTN_SMEM>>>(p_map, p_ft, p_v, p_at);

    // 5) x_out = gamma*(attn @ wr^T + br) + win   (window-reversed scatter)
    gemm_cp_kernel<1><<<dim3(8, 392), 256, GEMM_SMEM>>>(
        p_at, p_wrr, br, nullptr, x_out, nullptr, nullptr, p_win, gamma);
}

// round 8
// speedup vs baseline: 1.4855x; 1.4447x over previous
#include <cuda_runtime.h>
#include <cuda_bf16.h>
#include <cstdint>

// Problem constants (fixed by setup_inputs)
#define BATCH 16
#define HH 56
#define WW_ 56
#define CC 1024
#define KK 150
#define WS 7
#define L_TOK (HH*WW_)            // 3136
#define NTOK (BATCH*L_TOK)        // 50176 token rows (window-layout rows)
#define NWIN (NTOK/49)            // 1024 windows

// ---------------- device scratch (static globals; no runtime alloc) -------------
__device__ float sc_win [50176ull*1024];    // LN output fp32 (residual), logical ch
__device__ float sc_wint[50176ull*1024];    // LN output tf32-rounded, K-PERMUTED
__device__ float sc_map [50176ull*150];     // seg_map  [row][K]
__device__ float sc_ft  [50176ull*150];     // seg_ft   [row][K]
__device__ float sc_p   [50176ull*1024];    // P = win @ (wv^T wr^T) + c2, LOGICAL ch
__device__ float sc_wvt [1024ull*1024];     // wv transposed, rounded + j-permuted
__device__ float sc_wrr [1024ull*1024];     // wr rounded + j-permuted
__device__ float sc_bp  [1024ull*1024];     // Bp = wr@wv, rounded + k-permuted
__device__ float sc_wqk [384ull*1024];      // [wq;wk;zeros] rounded + K-permuted
__device__ float sc_c2  [1024];             // wr@bv + br

// ---------------- helpers -------------------------------------------------------
__device__ __forceinline__ float f2tf32(float x) {
    unsigned u;
    asm("cvt.rna.tf32.f32 %0, %1;" : "=r"(u) : "f"(x));
    return __uint_as_float(u);
}

// fragment-friendly K permutation, within each 32-column (=128B) block
__device__ __forceinline__ int permk(int c) {
    return (c & ~31) + ((c & 3) << 3) + (((c >> 3) & 3) << 1) + ((c >> 2) & 1);
}

__device__ __forceinline__ void mma_tf32(float (&c)[4], const unsigned (&a)[4],
                                         const unsigned (&b)[2]) {
    asm volatile(
        "mma.sync.aligned.m16n8k8.row.col.f32.tf32.tf32.f32 "
        "{%0,%1,%2,%3}, {%4,%5,%6,%7}, {%8,%9}, {%0,%1,%2,%3};\n"
        : "+f"(c[0]), "+f"(c[1]), "+f"(c[2]), "+f"(c[3])
        : "r"(a[0]), "r"(a[1]), "r"(a[2]), "r"(a[3]), "r"(b[0]), "r"(b[1]));
}

__device__ __forceinline__ uint32_t smem_u32(const void* p) {
    uint32_t a;
    asm("{ .reg .u64 t; cvta.to.shared.u64 t, %1; cvt.u32.u64 %0, t; }"
        : "=r"(a) : "l"(p));
    return a;
}

// row in window layout -> token index (b*3136 + l) in image layout
__device__ __forceinline__ int row_to_token(int rr) {
    int wI = rr / 49;
    int tI = rr - wI * 49;
    int b  = wI >> 6;
    int wl = wI & 63;
    int i  = tI / 7;
    int j  = tI - i * 7;
    int gr = (wl >> 3) * 7 + i;
    int gc = (wl & 7) * 7 + j;
    return b * L_TOK + gr * WW_ + gc;
}

// ---------------- weight prep: round to tf32 + K-permute ------------------------
__global__ void __launch_bounds__(256) prep_weights_kernel(
    const float* __restrict__ wq, const float* __restrict__ wk,
    const float* __restrict__ wv, const float* __restrict__ wr,
    float* __restrict__ owqk, float* __restrict__ owvt, float* __restrict__ owr)
{
    int t = blockIdx.x * 256 + threadIdx.x;       // 0..262143
    {
        int row = t >> 8;
        int k0  = (t & 255) * 4;
        size_t base = (size_t)row * 1024;
        // wr: rounded + j-permuted (A operand of weight GEMM)
        float4 w = *reinterpret_cast<const float4*>(wr + base + k0);
        owr[base + permk(k0 + 0)] = f2tf32(w.x);
        owr[base + permk(k0 + 1)] = f2tf32(w.y);
        owr[base + permk(k0 + 2)] = f2tf32(w.z);
        owr[base + permk(k0 + 3)] = f2tf32(w.w);
        // wv TRANSPOSED: owvt[n][permk(j)] = wv[j][n]  (B operand of weight GEMM)
        #pragma unroll
        for (int q = 0; q < 4; q++) {
            int j = k0 + q;
            owvt[base + permk(j)] = f2tf32(wv[(size_t)j * 1024 + row]);
        }
    }
    if (t < 384 * 256) {   // packed [wq;wk;zeros]: 384 rows
        int row = t >> 8;
        int k0  = (t & 255) * 4;
        float4 v = make_float4(0.f, 0.f, 0.f, 0.f);
        if (row < 150)
            v = *reinterpret_cast<const float4*>(wq + (size_t)row * 1024 + k0);
        else if (row < 300)
            v = *reinterpret_cast<const float4*>(wk + (size_t)(row - 150) * 1024 + k0);
        size_t base = (size_t)row * 1024;
        owqk[base + permk(k0 + 0)] = f2tf32(v.x);
        owqk[base + permk(k0 + 1)] = f2tf32(v.y);
        owqk[base + permk(k0 + 2)] = f2tf32(v.z);
        owqk[base + permk(k0 + 3)] = f2tf32(v.w);
    }
}

// c2[c] = sum_k wr[c][k]*bv[k] + br[c]    (one block per output c)
__global__ void __launch_bounds__(128) c2_kernel(
    const float* __restrict__ wr, const float* __restrict__ bv,
    const float* __restrict__ br, float* __restrict__ c2)
{
    const int c   = blockIdx.x;
    const int tid = threadIdx.x;
    float s = 0.f;
    #pragma unroll 4
    for (int k = tid; k < 1024; k += 128)
        s += wr[(size_t)c * 1024 + k] * bv[k];
    #pragma unroll
    for (int off = 16; off > 0; off >>= 1)
        s += __shfl_xor_sync(0xffffffff, s, off);
    __shared__ float red[4];
    if ((tid & 31) == 0) red[tid >> 5] = s;
    __syncthreads();
    if (tid == 0) c2[c] = red[0] + red[1] + red[2] + red[3] + br[c];
}

// ---------------- LayerNorm + window partition ----------------------------------
__global__ void __launch_bounds__(256) ln_win_kernel(
    const float* __restrict__ x, const float* __restrict__ nw,
    const float* __restrict__ nb, float* __restrict__ win,
    float* __restrict__ winr)
{
    const int token = blockIdx.x;
    const int tid   = threadIdx.x;
    const int b   = token / L_TOK;
    const int l   = token - b * L_TOK;
    const int row = l / WW_;
    const int col = l - row * WW_;
    const int w   = b * 64 + (row / 7) * 8 + (col / 7);
    const int t   = (row % 7) * 7 + (col % 7);

    const float4* xp = reinterpret_cast<const float4*>(x + (size_t)token * CC);
    float4 v = xp[tid];
    float s  = v.x + v.y + v.z + v.w;
    float s2 = v.x*v.x + v.y*v.y + v.z*v.z + v.w*v.w;

    #pragma unroll
    for (int off = 16; off > 0; off >>= 1) {
        s  += __shfl_xor_sync(0xffffffff, s,  off);
        s2 += __shfl_xor_sync(0xffffffff, s2, off);
    }
    __shared__ float red0[8], red1[8];
    __shared__ float s_mu, s_rs;
    const int warp = tid >> 5, lane = tid & 31;
    if (lane == 0) { red0[warp] = s; red1[warp] = s2; }
    __syncthreads();
    if (tid == 0) {
        float t0 = 0.f, t1 = 0.f;
        #pragma unroll
        for (int i = 0; i < 8; i++) { t0 += red0[i]; t1 += red1[i]; }
        float mu  = t0 * (1.0f / CC);
        float var = t1 * (1.0f / CC) - mu * mu;
        s_mu = mu;
        s_rs = rsqrtf(var + 1e-5f);
    }
    __syncthreads();
    const float mu = s_mu, rs = s_rs;

    float4 w4 = reinterpret_cast<const float4*>(nw)[tid];
    float4 b4 = reinterpret_cast<const float4*>(nb)[tid];
    float4 o;
    o.x = (v.x - mu) * rs * w4.x + b4.x;
    o.y = (v.y - mu) * rs * w4.y + b4.y;
    o.z = (v.z - mu) * rs * w4.z + b4.z;
    o.w = (v.w - mu) * rs * w4.w + b4.w;
    const size_t dst = (size_t)(w * 49 + t) * CC;
    reinterpret_cast<float4*>(win + dst)[tid] = o;
    const int c0 = tid * 4;
    winr[dst + permk(c0 + 0)] = f2tf32(o.x);
    winr[dst + permk(c0 + 1)] = f2tf32(o.y);
    winr[dst + permk(c0 + 2)] = f2tf32(o.z);
    winr[dst + permk(c0 + 3)] = f2tf32(o.w);
}

// ---------------- TF32 GEMM with cp.async pipeline + permuted fragments ---------
// C[M,N] = A[M,1024] @ B[N,1024]^T ;  A,B pre-rounded to tf32 and K-permuted.
// EPI 0 (P):  out0[rr*1024 + col]      = v + bias[col]   (LOGICAL store)
// EPI 2 (QK): col<150  -> v+bias[col]      -> out0[rr*150+col], out1[token*150+col]
//             col<300  -> v+bias2[col-150] -> out2[rr*150+col-150]
// EPI 3 (Wc): out0[rr*1024 + permk(col)] = tf32(v)       (B-operand for P GEMM)
#define NS 3
#define STG_F (128*36)
#define STAGE_F (2*STG_F)
#define GEMM_SMEM (NS*STAGE_F*4)      // 110592 bytes

template <int EPI>
__global__ void __launch_bounds__(256, 2) gemm_cp_kernel(
    const float* __restrict__ A, const float* __restrict__ B,
    const float* __restrict__ bias, const float* __restrict__ bias2,
    float* __restrict__ out0, float* __restrict__ out1, float* __restrict__ out2)
{
    extern __shared__ float sm[];
    const int tid  = threadIdx.x;
    const int warp = tid >> 5, lane = tid & 31;
    const int wm   = warp >> 2, wn = warp & 3;      // 2x4 warp grid, 64x32 tiles
    const int grp  = lane >> 2, tid4 = lane & 3;
    const int blockN = blockIdx.x * 128;
    const int blockM = blockIdx.y * 128;
    const uint32_t sbase = smem_u32(sm);

    float acc[4][4][4];
    #pragma unroll
    for (int a = 0; a < 4; a++)
        #pragma unroll
        for (int b = 0; b < 4; b++)
            #pragma unroll
            for (int c = 0; c < 4; c++) acc[a][b][c] = 0.f;

    auto issue = [&](int kt) {
        if (kt < 32) {
            const int s  = kt - (kt / NS) * NS;
            const int k0 = kt * 32;
            const uint32_t ab = sbase + (uint32_t)s * (STAGE_F * 4);
            #pragma unroll
            for (int i = 0; i < 4; i++) {
                int idx = i * 256 + tid;           // 0..1023
                int row = idx >> 3, ch = idx & 7;
                uint32_t off = (uint32_t)(row * 36 + ch * 4) * 4;
                const float* sa = A + (size_t)(blockM + row) * 1024 + k0 + ch * 4;
                asm volatile("cp.async.cg.shared.global [%0], [%1], 16;\n"
                             :: "r"(ab + off), "l"(sa));
                const float* sb = B + (size_t)(blockN + row) * 1024 + k0 + ch * 4;
                asm volatile("cp.async.cg.shared.global [%0], [%1], 16;\n"
                             :: "r"(ab + STG_F * 4 + off), "l"(sb));
            }
        }
        asm volatile("cp.async.commit_group;\n" ::: "memory");
    };

    issue(0);
    issue(1);

    for (int kt = 0; kt < 32; kt++) {
        asm volatile("cp.async.wait_group 1;\n" ::: "memory");
        __syncthreads();
        issue(kt + 2);

        const float* As = sm + (kt - (kt / NS) * NS) * STAGE_F;
        const float* Bs = As + STG_F;

        #pragma unroll
        for (int kp = 0; kp < 2; kp++) {
            float4 bf[4];
            #pragma unroll
            for (int nt = 0; nt < 4; nt++)
                bf[nt] = *reinterpret_cast<const float4*>(
                    &Bs[(wn * 32 + nt * 8 + grp) * 36 + tid4 * 8 + kp * 4]);
            #pragma unroll
            for (int mt = 0; mt < 4; mt++) {
                const int r = wm * 64 + mt * 16 + grp;
                float4 a0 = *reinterpret_cast<const float4*>(
                    &As[r * 36 + tid4 * 8 + kp * 4]);
                float4 a1 = *reinterpret_cast<const float4*>(
                    &As[(r + 8) * 36 + tid4 * 8 + kp * 4]);
                unsigned af0[4] = {__float_as_uint(a0.x), __float_as_uint(a1.x),
                                   __float_as_uint(a0.y), __float_as_uint(a1.y)};
                unsigned af1[4] = {__float_as_uint(a0.z), __float_as_uint(a1.z),
                                   __float_as_uint(a0.w), __float_as_uint(a1.w)};
                #pragma unroll
                for (int nt = 0; nt < 4; nt++) {
                    unsigned b0[2] = {__float_as_uint(bf[nt].x),
                                      __float_as_uint(bf[nt].y)};
                    mma_tf32(acc[mt][nt], af0, b0);
                    unsigned b1[2] = {__float_as_uint(bf[nt].z),
                                      __float_as_uint(bf[nt].w)};
                    mma_tf32(acc[mt][nt], af1, b1);
                }
            }
        }
    }

    // -------- epilogue --------
    #pragma unroll
    for (int mt = 0; mt < 4; mt++) {
        const int rbase = blockM + wm * 64 + mt * 16 + grp;
        #pragma unroll
        for (int half = 0; half < 2; half++) {
            const int rr = rbase + half * 8;
            int token = 0;
            if (EPI == 2) token = row_to_token(rr);
            #pragma unroll
            for (int nt = 0; nt < 4; nt++) {
                #pragma unroll
                for (int cc = 0; cc < 2; cc++) {
                    const int col = blockN + wn * 32 + nt * 8 + tid4 * 2 + cc;
                    const float v = acc[mt][nt][half * 2 + cc];
                    if (EPI == 0) {
                        out0[(size_t)rr * 1024 + col] = v + bias[col];
                    } else if (EPI == 3) {
                        out0[(size_t)rr * 1024 + permk(col)] = f2tf32(v);
                    } else {
                        if (col < 150) {
                            float o = v + bias[col];
                            out0[(size_t)rr * 150 + col] = o;
                            out1[(size_t)token * 150 + col] = o;
                        } else if (col < 300) {
                            out2[(size_t)rr * 150 + (col - 150)] =
                                v + bias2[col - 150];
                        }
                    }
                }
            }
        }
    }
}

// ---------------- per-window attention + fused output epilogue ------------------
// S = softmax(seg_map @ seg_ft^T); x_out[token] = gamma*(S@P)[n] + win[row]
#define SMAP_OFF 0
#define SFT_OFF  (49*151)
#define SS_OFF   (49*512)
#define STOK_OFF (49*512 + 49*49)
#define ATTN_SMEM ((49*512 + 49*49 + 64) * 4)

__global__ void __launch_bounds__(256) attn_kernel(
    const float* __restrict__ segmap, const float* __restrict__ segft,
    const float* __restrict__ pmat, const float* __restrict__ win,
    float* __restrict__ xout, const float* __restrict__ gammap)
{
    extern __shared__ float sm[];
    float* sMap = sm + SMAP_OFF;
    float* sFt  = sm + SFT_OFF;
    float* sS   = sm + SS_OFF;
    int*   sTok = reinterpret_cast<int*>(sm + STOK_OFF);
    float* sV   = sm;

    const int w   = blockIdx.x;
    const int tid = threadIdx.x;
    const float gm = __ldg(gammap);

    if (tid < 49) sTok[tid] = row_to_token(w * 49 + tid);
    for (int idx = tid; idx < 49 * 150; idx += 256) {
        int n = idx / 150, k = idx - n * 150;
        sMap[n * 151 + k] = segmap[(size_t)(w * 49 + n) * 150 + k];
        sFt [n * 151 + k] = segft [(size_t)(w * 49 + n) * 150 + k];
    }
    __syncthreads();

    for (int p = tid; p < 49 * 49; p += 256) {
        int n = p / 49, m = p - n * 49;
        float acc = 0.f;
        const float* qr = sMap + n * 151;
        const float* kr = sFt + m * 151;
        #pragma unroll 5
        for (int k = 0; k < 150; k++) acc += qr[k] * kr[k];
        sS[n * 49 + m] = acc;
    }
    __syncthreads();

    if (tid < 49) {
        float* row = sS + tid * 49;
        float mx = -1e30f;
        #pragma unroll
        for (int m = 0; m < 49; m++) mx = fmaxf(mx, row[m]);
        float sum = 0.f;
        #pragma unroll
        for (int m = 0; m < 49; m++) {
            float e = __expf(row[m] - mx);
            row[m] = e;
            sum += e;
        }
        float inv = 1.0f / sum;
        #pragma unroll
        for (int m = 0; m < 49; m++) row[m] *= inv;
    }
    __syncthreads();

    for (int chunk = 0; chunk < 2; chunk++) {
        const int c0 = chunk * 512;
        for (int q = tid; q < 49 * 128; q += 256) {
            int m = q / 128, c4 = q - m * 128;
            reinterpret_cast<float4*>(sV)[m * 128 + c4] =
                *reinterpret_cast<const float4*>(
                    pmat + (size_t)(w * 49 + m) * 1024 + c0 + c4 * 4);
        }
        __syncthreads();

        for (int task = tid; task < 49 * 128; task += 256) {
            int n = task / 128, cg = task - n * 128;
            float4 acc = make_float4(0.f, 0.f, 0.f, 0.f);
            const float* srow = sS + n * 49;
            #pragma unroll 7
            for (int m = 0; m < 49; m++) {
                float s = srow[m];
                float4 v = reinterpret_cast<const float4*>(sV)[m * 128 + cg];
                acc.x += s * v.x; acc.y += s * v.y;
                acc.z += s * v.z; acc.w += s * v.w;
            }
            // fused: x_out = gamma*(S@P) + win, window-reversed scatter
            float4 r4 = *reinterpret_cast<const float4*>(
                win + (size_t)(w * 49 + n) * 1024 + c0 + cg * 4);
            float4 o;
            o.x = gm * acc.x + r4.x;
            o.y = gm * acc.y + r4.y;
            o.z = gm * acc.z + r4.z;
            o.w = gm * acc.w + r4.w;
            *reinterpret_cast<float4*>(
                xout + (size_t)sTok[n] * 1024 + c0 + cg * 4) = o;
        }
        __syncthreads();
    }
}

// ---------------- launch --------------------------------------------------------
extern "C" void kernel_launch(void* const* d_in, const int* in_sizes, int n_in,
                              void* d_out, int out_size)
{
    const float* x     = (const float*)d_in[0];
    const float* nw    = (const float*)d_in[1];
    const float* nb    = (const float*)d_in[2];
    const float* wq    = (const float*)d_in[3];
    const float* bq    = (const float*)d_in[4];
    const float* wk    = (const float*)d_in[5];
    const float* bk    = (const float*)d_in[6];
    const float* wv    = (const float*)d_in[7];
    const float* bv    = (const float*)d_in[8];
    const float* wr    = (const float*)d_in[9];
    const float* br    = (const float*)d_in[10];
    const float* gamma = (const float*)d_in[11];

    float* out     = (float*)d_out;
    float* sem_out = out;                                    // (B,L,K) first
    float* x_out   = out + (size_t)NTOK * KK;                // then (B,L,C)

    float *p_win, *p_wint, *p_map, *p_ft, *p_p, *p_wvt, *p_wrr, *p_bp, *p_wqk, *p_c2;
    cudaGetSymbolAddress((void**)&p_win,  sc_win);
    cudaGetSymbolAddress((void**)&p_wint, sc_wint);
    cudaGetSymbolAddress((void**)&p_map,  sc_map);
    cudaGetSymbolAddress((void**)&p_ft,   sc_ft);
    cudaGetSymbolAddress((void**)&p_p,    sc_p);
    cudaGetSymbolAddress((void**)&p_wvt,  sc_wvt);
    cudaGetSymbolAddress((void**)&p_wrr,  sc_wrr);
    cudaGetSymbolAddress((void**)&p_bp,   sc_bp);
    cudaGetSymbolAddress((void**)&p_wqk,  sc_wqk);
    cudaGetSymbolAddress((void**)&p_c2,   sc_c2);

    cudaFuncSetAttribute(gemm_cp_kernel<0>,
                         cudaFuncAttributeMaxDynamicSharedMemorySize, GEMM_SMEM);
    cudaFuncSetAttribute(gemm_cp_kernel<2>,
                         cudaFuncAttributeMaxDynamicSharedMemorySize, GEMM_SMEM);
    cudaFuncSetAttribute(gemm_cp_kernel<3>,
                         cudaFuncAttributeMaxDynamicSharedMemorySize, GEMM_SMEM);
    cudaFuncSetAttribute(attn_kernel,
                         cudaFuncAttributeMaxDynamicSharedMemorySize, ATTN_SMEM);

    // 0) weight prep: [wq;wk] packed, wr rounded, wv transposed; c2 = wr@bv + br
    prep_weights_kernel<<<1024, 256>>>(wq, wk, wv, wr, p_wqk, p_wvt, p_wrr);
    c2_kernel<<<1024, 128>>>(wr, bv, br, p_c2);

    // 1) Bp = wr @ wv  (combined channel weight; stored tf32 + k-permuted)
    gemm_cp_kernel<3><<<dim3(8, 8), 256, GEMM_SMEM>>>(
        p_wrr, p_wvt, nullptr, nullptr, p_bp, nullptr, nullptr);

    // 2) LayerNorm + window partition (fp32 residual + tf32-permuted GEMM copy)
    ln_win_kernel<<<NTOK, 256>>>(x, nw, nb, p_win, p_wint);

    // 3) fused Q/K projection: [seg_map | seg_ft] = win @ [wq;wk]^T + [bq;bk]
    gemm_cp_kernel<2><<<dim3(3, 392), 256, GEMM_SMEM>>>(
        p_wint, p_wqk, bq, bk, p_map, sem_out, p_ft);

    // 4) P = win @ Bp^T + c2   (replaces BOTH V-proj and R-proj GEMMs)
    gemm_cp_kernel<0><<<dim3(8, 392), 256, GEMM_SMEM>>>(
        p_wint, p_bp, p_c2, nullptr, p_p, nullptr, nullptr);

    // 5) attention + fused gamma/residual/window-reverse epilogue -> x_out
    attn_kernel<<<NWIN, 256, ATTN_SMEM>>>(p_map, p_ft, p_p, p_win, x_out, gamma);
}

// round 9
// speedup vs baseline: 1.7436x; 1.1738x over previous
#include <cuda_runtime.h>
#include <cuda_bf16.h>
#include <cstdint>

// Problem constants (fixed by setup_inputs)
#define BATCH 16
#define HH 56
#define WW_ 56
#define CC 1024
#define KK 150
#define WS 7
#define L_TOK (HH*WW_)            // 3136
#define NTOK (BATCH*L_TOK)        // 50176 token rows (window-layout rows)
#define NWIN (NTOK/49)            // 1024 windows

// ---------------- device scratch (static globals; no runtime alloc) -------------
__device__ float sc_win [50176ull*1024];    // LN output fp32 (residual), logical ch
__device__ float sc_wint[50176ull*1024];    // LN output tf32-rounded, K-PERMUTED
__device__ float sc_map [50176ull*150];     // seg_map  [row][K]
__device__ float sc_ft  [50176ull*150];     // seg_ft   [row][K]
__device__ float sc_p   [50176ull*1024];    // P = win @ (wv^T wr^T) + c2, tf32, logical
__device__ float sc_wvt [1024ull*1024];     // wv transposed, rounded + j-permuted
__device__ float sc_wrr [1024ull*1024];     // wr rounded + j-permuted
__device__ float sc_bp  [1024ull*1024];     // Bp = wr@wv, rounded + k-permuted
__device__ float sc_wqk [384ull*1024];      // [wq;wk;zeros] rounded + K-permuted
__device__ float sc_c2  [1024];             // wr@bv + br

// ---------------- helpers -------------------------------------------------------
__device__ __forceinline__ float f2tf32(float x) {
    unsigned u;
    asm("cvt.rna.tf32.f32 %0, %1;" : "=r"(u) : "f"(x));
    return __uint_as_float(u);
}

// fragment-friendly K permutation, within each 32-column (=128B) block
__device__ __forceinline__ int permk(int c) {
    return (c & ~31) + ((c & 3) << 3) + (((c >> 3) & 3) << 1) + ((c >> 2) & 1);
}

__device__ __forceinline__ void mma_tf32(float (&c)[4], const unsigned (&a)[4],
                                         const unsigned (&b)[2]) {
    asm volatile(
        "mma.sync.aligned.m16n8k8.row.col.f32.tf32.tf32.f32 "
        "{%0,%1,%2,%3}, {%4,%5,%6,%7}, {%8,%9}, {%0,%1,%2,%3};\n"
        : "+f"(c[0]), "+f"(c[1]), "+f"(c[2]), "+f"(c[3])
        : "r"(a[0]), "r"(a[1]), "r"(a[2]), "r"(a[3]), "r"(b[0]), "r"(b[1]));
}

__device__ __forceinline__ uint32_t smem_u32(const void* p) {
    uint32_t a;
    asm("{ .reg .u64 t; cvta.to.shared.u64 t, %1; cvt.u32.u64 %0, t; }"
        : "=r"(a) : "l"(p));
    return a;
}

// row in window layout -> token index (b*3136 + l) in image layout
__device__ __forceinline__ int row_to_token(int rr) {
    int wI = rr / 49;
    int tI = rr - wI * 49;
    int b  = wI >> 6;
    int wl = wI & 63;
    int i  = tI / 7;
    int j  = tI - i * 7;
    int gr = (wl >> 3) * 7 + i;
    int gc = (wl & 7) * 7 + j;
    return b * L_TOK + gr * WW_ + gc;
}

// ---------------- weight prep: round to tf32 + K-permute ------------------------
__global__ void __launch_bounds__(256) prep_weights_kernel(
    const float* __restrict__ wq, const float* __restrict__ wk,
    const float* __restrict__ wv, const float* __restrict__ wr,
    float* __restrict__ owqk, float* __restrict__ owvt, float* __restrict__ owr)
{
    int t = blockIdx.x * 256 + threadIdx.x;       // 0..262143
    {
        int row = t >> 8;
        int k0  = (t & 255) * 4;
        size_t base = (size_t)row * 1024;
        // wr: rounded + j-permuted (A operand of weight GEMM)
        float4 w = *reinterpret_cast<const float4*>(wr + base + k0);
        owr[base + permk(k0 + 0)] = f2tf32(w.x);
        owr[base + permk(k0 + 1)] = f2tf32(w.y);
        owr[base + permk(k0 + 2)] = f2tf32(w.z);
        owr[base + permk(k0 + 3)] = f2tf32(w.w);
        // wv TRANSPOSED: owvt[n][permk(j)] = wv[j][n]  (B operand of weight GEMM)
        #pragma unroll
        for (int q = 0; q < 4; q++) {
            int j = k0 + q;
            owvt[base + permk(j)] = f2tf32(wv[(size_t)j * 1024 + row]);
        }
    }
    if (t < 384 * 256) {   // packed [wq;wk;zeros]: 384 rows
        int row = t >> 8;
        int k0  = (t & 255) * 4;
        float4 v = make_float4(0.f, 0.f, 0.f, 0.f);
        if (row < 150)
            v = *reinterpret_cast<const float4*>(wq + (size_t)row * 1024 + k0);
        else if (row < 300)
            v = *reinterpret_cast<const float4*>(wk + (size_t)(row - 150) * 1024 + k0);
        size_t base = (size_t)row * 1024;
        owqk[base + permk(k0 + 0)] = f2tf32(v.x);
        owqk[base + permk(k0 + 1)] = f2tf32(v.y);
        owqk[base + permk(k0 + 2)] = f2tf32(v.z);
        owqk[base + permk(k0 + 3)] = f2tf32(v.w);
    }
}

// c2[c] = sum_k wr[c][k]*bv[k] + br[c]    (one block per output c)
__global__ void __launch_bounds__(128) c2_kernel(
    const float* __restrict__ wr, const float* __restrict__ bv,
    const float* __restrict__ br, float* __restrict__ c2)
{
    const int c   = blockIdx.x;
    const int tid = threadIdx.x;
    float s = 0.f;
    #pragma unroll 4
    for (int k = tid; k < 1024; k += 128)
        s += wr[(size_t)c * 1024 + k] * bv[k];
    #pragma unroll
    for (int off = 16; off > 0; off >>= 1)
        s += __shfl_xor_sync(0xffffffff, s, off);
    __shared__ float red[4];
    if ((tid & 31) == 0) red[tid >> 5] = s;
    __syncthreads();
    if (tid == 0) c2[c] = red[0] + red[1] + red[2] + red[3] + br[c];
}

// ---------------- LayerNorm + window partition ----------------------------------
__global__ void __launch_bounds__(256) ln_win_kernel(
    const float* __restrict__ x, const float* __restrict__ nw,
    const float* __restrict__ nb, float* __restrict__ win,
    float* __restrict__ winr)
{
    const int token = blockIdx.x;
    const int tid   = threadIdx.x;
    const int b   = token / L_TOK;
    const int l   = token - b * L_TOK;
    const int row = l / WW_;
    const int col = l - row * WW_;
    const int w   = b * 64 + (row / 7) * 8 + (col / 7);
    const int t   = (row % 7) * 7 + (col % 7);

    const float4* xp = reinterpret_cast<const float4*>(x + (size_t)token * CC);
    float4 v = xp[tid];
    float s  = v.x + v.y + v.z + v.w;
    float s2 = v.x*v.x + v.y*v.y + v.z*v.z + v.w*v.w;

    #pragma unroll
    for (int off = 16; off > 0; off >>= 1) {
        s  += __shfl_xor_sync(0xffffffff, s,  off);
        s2 += __shfl_xor_sync(0xffffffff, s2, off);
    }
    __shared__ float red0[8], red1[8];
    __shared__ float s_mu, s_rs;
    const int warp = tid >> 5, lane = tid & 31;
    if (lane == 0) { red0[warp] = s; red1[warp] = s2; }
    __syncthreads();
    if (tid == 0) {
        float t0 = 0.f, t1 = 0.f;
        #pragma unroll
        for (int i = 0; i < 8; i++) { t0 += red0[i]; t1 += red1[i]; }
        float mu  = t0 * (1.0f / CC);
        float var = t1 * (1.0f / CC) - mu * mu;
        s_mu = mu;
        s_rs = rsqrtf(var + 1e-5f);
    }
    __syncthreads();
    const float mu = s_mu, rs = s_rs;

    float4 w4 = reinterpret_cast<const float4*>(nw)[tid];
    float4 b4 = reinterpret_cast<const float4*>(nb)[tid];
    float4 o;
    o.x = (v.x - mu) * rs * w4.x + b4.x;
    o.y = (v.y - mu) * rs * w4.y + b4.y;
    o.z = (v.z - mu) * rs * w4.z + b4.z;
    o.w = (v.w - mu) * rs * w4.w + b4.w;
    const size_t dst = (size_t)(w * 49 + t) * CC;
    reinterpret_cast<float4*>(win + dst)[tid] = o;
    const int c0 = tid * 4;
    winr[dst + permk(c0 + 0)] = f2tf32(o.x);
    winr[dst + permk(c0 + 1)] = f2tf32(o.y);
    winr[dst + permk(c0 + 2)] = f2tf32(o.z);
    winr[dst + permk(c0 + 3)] = f2tf32(o.w);
}

// ---------------- TF32 GEMM with cp.async pipeline + permuted fragments ---------
// C[M,N] = A[M,1024] @ B[N,1024]^T ;  A,B pre-rounded to tf32 and K-permuted.
// EPI 0 (P):  out0[rr*1024 + col]      = tf32(v + bias[col])  (MMA-ready logical)
// EPI 2 (QK): col<150  -> v+bias[col]      -> out0[rr*150+col], out1[token*150+col]
//             col<300  -> v+bias2[col-150] -> out2[rr*150+col-150]
// EPI 3 (Wc): out0[rr*1024 + permk(col)] = tf32(v)       (B-operand for P GEMM)
#define NS 3
#define STG_F (128*36)
#define STAGE_F (2*STG_F)
#define GEMM_SMEM (NS*STAGE_F*4)      // 110592 bytes

template <int EPI>
__global__ void __launch_bounds__(256, 2) gemm_cp_kernel(
    const float* __restrict__ A, const float* __restrict__ B,
    const float* __restrict__ bias, const float* __restrict__ bias2,
    float* __restrict__ out0, float* __restrict__ out1, float* __restrict__ out2)
{
    extern __shared__ float sm[];
    const int tid  = threadIdx.x;
    const int warp = tid >> 5, lane = tid & 31;
    const int wm   = warp >> 2, wn = warp & 3;      // 2x4 warp grid, 64x32 tiles
    const int grp  = lane >> 2, tid4 = lane & 3;
    const int blockN = blockIdx.x * 128;
    const int blockM = blockIdx.y * 128;
    const uint32_t sbase = smem_u32(sm);

    float acc[4][4][4];
    #pragma unroll
    for (int a = 0; a < 4; a++)
        #pragma unroll
        for (int b = 0; b < 4; b++)
            #pragma unroll
            for (int c = 0; c < 4; c++) acc[a][b][c] = 0.f;

    auto issue = [&](int kt) {
        if (kt < 32) {
            const int s  = kt - (kt / NS) * NS;
            const int k0 = kt * 32;
            const uint32_t ab = sbase + (uint32_t)s * (STAGE_F * 4);
            #pragma unroll
            for (int i = 0; i < 4; i++) {
                int idx = i * 256 + tid;           // 0..1023
                int row = idx >> 3, ch = idx & 7;
                uint32_t off = (uint32_t)(row * 36 + ch * 4) * 4;
                const float* sa = A + (size_t)(blockM + row) * 1024 + k0 + ch * 4;
                asm volatile("cp.async.cg.shared.global [%0], [%1], 16;\n"
                             :: "r"(ab + off), "l"(sa));
                const float* sb = B + (size_t)(blockN + row) * 1024 + k0 + ch * 4;
                asm volatile("cp.async.cg.shared.global [%0], [%1], 16;\n"
                             :: "r"(ab + STG_F * 4 + off), "l"(sb));
            }
        }
        asm volatile("cp.async.commit_group;\n" ::: "memory");
    };

    issue(0);
    issue(1);

    for (int kt = 0; kt < 32; kt++) {
        asm volatile("cp.async.wait_group 1;\n" ::: "memory");
        __syncthreads();
        issue(kt + 2);

        const float* As = sm + (kt - (kt / NS) * NS) * STAGE_F;
        const float* Bs = As + STG_F;

        #pragma unroll
        for (int kp = 0; kp < 2; kp++) {
            float4 bf[4];
            #pragma unroll
            for (int nt = 0; nt < 4; nt++)
                bf[nt] = *reinterpret_cast<const float4*>(
                    &Bs[(wn * 32 + nt * 8 + grp) * 36 + tid4 * 8 + kp * 4]);
            #pragma unroll
            for (int mt = 0; mt < 4; mt++) {
                const int r = wm * 64 + mt * 16 + grp;
                float4 a0 = *reinterpret_cast<const float4*>(
                    &As[r * 36 + tid4 * 8 + kp * 4]);
                float4 a1 = *reinterpret_cast<const float4*>(
                    &As[(r + 8) * 36 + tid4 * 8 + kp * 4]);
                unsigned af0[4] = {__float_as_uint(a0.x), __float_as_uint(a1.x),
                                   __float_as_uint(a0.y), __float_as_uint(a1.y)};
                unsigned af1[4] = {__float_as_uint(a0.z), __float_as_uint(a1.z),
                                   __float_as_uint(a0.w), __float_as_uint(a1.w)};
                #pragma unroll
                for (int nt = 0; nt < 4; nt++) {
                    unsigned b0[2] = {__float_as_uint(bf[nt].x),
                                      __float_as_uint(bf[nt].y)};
                    mma_tf32(acc[mt][nt], af0, b0);
                    unsigned b1[2] = {__float_as_uint(bf[nt].z),
                                      __float_as_uint(bf[nt].w)};
                    mma_tf32(acc[mt][nt], af1, b1);
                }
            }
        }
    }

    // -------- epilogue --------
    #pragma unroll
    for (int mt = 0; mt < 4; mt++) {
        const int rbase = blockM + wm * 64 + mt * 16 + grp;
        #pragma unroll
        for (int half = 0; half < 2; half++) {
            const int rr = rbase + half * 8;
            int token = 0;
            if (EPI == 2) token = row_to_token(rr);
            #pragma unroll
            for (int nt = 0; nt < 4; nt++) {
                #pragma unroll
                for (int cc = 0; cc < 2; cc++) {
                    const int col = blockN + wn * 32 + nt * 8 + tid4 * 2 + cc;
                    const float v = acc[mt][nt][half * 2 + cc];
                    if (EPI == 0) {
                        out0[(size_t)rr * 1024 + col] = f2tf32(v + bias[col]);
                    } else if (EPI == 3) {
                        out0[(size_t)rr * 1024 + permk(col)] = f2tf32(v);
                    } else {
                        if (col < 150) {
                            float o = v + bias[col];
                            out0[(size_t)rr * 150 + col] = o;
                            out1[(size_t)token * 150 + col] = o;
                        } else if (col < 300) {
                            out2[(size_t)rr * 150 + (col - 150)] =
                                v + bias2[col - 150];
                        }
                    }
                }
            }
        }
    }
}

// ---------------- per-window attention: FMA QK^T + softmax, MMA S@P -------------
// S = softmax(seg_map @ seg_ft^T); x_out[token] = gamma*(S@P)[n] + win[row]
// smem layout (floats):
//   region1 (aliased): sMap[49][151], sFt[49][151]   then   sP[56][264]
//   sS[64][60]  (A-operand, tf32-rounded, zero-padded k cols)
//   sTok[64]
#define APS 264
#define ASS 60
#define R_FT  (49*151)
#define R_S   (2*49*151)              // 14798
#define R_TOK (R_S + 64*ASS)          // +3840
#define ATTN_F (R_TOK + 64)
#define ATTN_SMEM (ATTN_F*4)          // 74808 bytes

__global__ void __launch_bounds__(256) attn_kernel(
    const float* __restrict__ segmap, const float* __restrict__ segft,
    const float* __restrict__ pmat, const float* __restrict__ win,
    float* __restrict__ xout, const float* __restrict__ gammap)
{
    extern __shared__ float sm[];
    float* sMap = sm;
    float* sFt  = sm + R_FT;
    float* sP   = sm;                 // aliases sMap/sFt after phase A
    float* sS   = sm + R_S;
    int*   sTok = reinterpret_cast<int*>(sm + R_TOK);

    const int w    = blockIdx.x;
    const int tid  = threadIdx.x;
    const int warp = tid >> 5, lane = tid & 31;
    const int grp  = lane >> 2, tid4 = lane & 3;
    const float gm = __ldg(gammap);

    if (tid < 49) sTok[tid] = row_to_token(w * 49 + tid);
    // zero S pad columns k=49..55 for valid rows (MMA k-padding must be 0)
    for (int i = tid; i < 49 * 7; i += 256)
        sS[(i / 7) * ASS + 49 + (i % 7)] = 0.f;
    // stage seg_map / seg_ft
    for (int idx = tid; idx < 49 * 150; idx += 256) {
        int n = idx / 150, k = idx - n * 150;
        sMap[n * 151 + k] = segmap[(size_t)(w * 49 + n) * 150 + k];
        sFt [n * 151 + k] = segft [(size_t)(w * 49 + n) * 150 + k];
    }
    __syncthreads();

    // S = Q K^T   (scalar FMA; 0.72 MFLOP per window)
    for (int p = tid; p < 49 * 49; p += 256) {
        int n = p / 49, m = p - n * 49;
        float acc = 0.f;
        const float* qr = sMap + n * 151;
        const float* kr = sFt + m * 151;
        #pragma unroll 5
        for (int k = 0; k < 150; k++) acc += qr[k] * kr[k];
        sS[n * ASS + m] = acc;
    }
    __syncthreads();

    // row softmax (49 threads), write tf32-rounded; others zero sP pad rows
    if (tid < 49) {
        float* row = sS + tid * ASS;
        float mx = -1e30f;
        #pragma unroll
        for (int m = 0; m < 49; m++) mx = fmaxf(mx, row[m]);
        float sum = 0.f;
        #pragma unroll
        for (int m = 0; m < 49; m++) {
            float e = __expf(row[m] - mx);
            row[m] = e;
            sum += e;
        }
        float inv = 1.0f / sum;
        #pragma unroll
        for (int m = 0; m < 49; m++) row[m] = f2tf32(row[m] * inv);
    }
    // zero sP rows 49..55 (k-padding of B; aliases dead sMap/sFt region)
    for (int i = tid; i < 7 * APS; i += 256)
        sP[(49 + i / APS) * APS + (i % APS)] = 0.f;
    __syncthreads();

    // S@P via tf32 MMA: 4 chunks of 256 channels
    const int n0 = warp * 32;
    for (int ch4 = 0; ch4 < 4; ch4++) {
        const int c0 = ch4 * 256;
        for (int q = tid; q < 49 * 64; q += 256) {
            int m = q >> 6, c4 = q & 63;
            *reinterpret_cast<float4*>(&sP[m * APS + c4 * 4]) =
                *reinterpret_cast<const float4*>(
                    pmat + (size_t)(w * 49 + m) * 1024 + c0 + c4 * 4);
        }
        __syncthreads();

        float acc[4][4][4];
        #pragma unroll
        for (int a = 0; a < 4; a++)
            #pragma unroll
            for (int b = 0; b < 4; b++)
                #pragma unroll
                for (int c = 0; c < 4; c++) acc[a][b][c] = 0.f;

        #pragma unroll
        for (int kk = 0; kk < 7; kk++) {
            const int k = kk * 8;
            unsigned bfr[4][2];
            #pragma unroll
            for (int nt = 0; nt < 4; nt++) {
                const int n = n0 + nt * 8 + grp;
                bfr[nt][0] = __float_as_uint(sP[(k + tid4) * APS + n]);
                bfr[nt][1] = __float_as_uint(sP[(k + tid4 + 4) * APS + n]);
            }
            #pragma unroll
            for (int mt = 0; mt < 4; mt++) {
                const int m = mt * 16 + grp;
                unsigned af[4] = {
                    __float_as_uint(sS[m * ASS + k + tid4]),
                    __float_as_uint(sS[(m + 8) * ASS + k + tid4]),
                    __float_as_uint(sS[m * ASS + k + tid4 + 4]),
                    __float_as_uint(sS[(m + 8) * ASS + k + tid4 + 4])};
                #pragma unroll
                for (int nt = 0; nt < 4; nt++)
                    mma_tf32(acc[mt][nt], af, bfr[nt]);
            }
        }

        // fused epilogue: x_out = gamma*D + win, window-reversed scatter
        #pragma unroll
        for (int mt = 0; mt < 4; mt++) {
            #pragma unroll
            for (int half = 0; half < 2; half++) {
                const int m = mt * 16 + half * 8 + grp;
                if (m < 49) {
                    const size_t wbase = (size_t)(w * 49 + m) * 1024 + c0;
                    const size_t obase = (size_t)sTok[m] * 1024 + c0;
                    #pragma unroll
                    for (int nt = 0; nt < 4; nt++) {
                        const int n = n0 + nt * 8 + tid4 * 2;
                        float2 r = *reinterpret_cast<const float2*>(win + wbase + n);
                        float2 o;
                        o.x = gm * acc[mt][nt][half * 2 + 0] + r.x;
                        o.y = gm * acc[mt][nt][half * 2 + 1] + r.y;
                        *reinterpret_cast<float2*>(xout + obase + n) = o;
                    }
                }
            }
        }
        __syncthreads();
    }
}

// ---------------- launch --------------------------------------------------------
extern "C" void kernel_launch(void* const* d_in, const int* in_sizes, int n_in,
                              void* d_out, int out_size)
{
    const float* x     = (const float*)d_in[0];
    const float* nw    = (const float*)d_in[1];
    const float* nb    = (const float*)d_in[2];
    const float* wq    = (const float*)d_in[3];
    const float* bq    = (const float*)d_in[4];
    const float* wk    = (const float*)d_in[5];
    const float* bk    = (const float*)d_in[6];
    const float* wv    = (const float*)d_in[7];
    const float* bv    = (const float*)d_in[8];
    const float* wr    = (const float*)d_in[9];
    const float* br    = (const float*)d_in[10];
    const float* gamma = (const float*)d_in[11];

    float* out     = (float*)d_out;
    float* sem_out = out;                                    // (B,L,K) first
    float* x_out   = out + (size_t)NTOK * KK;                // then (B,L,C)

    float *p_win, *p_wint, *p_map, *p_ft, *p_p, *p_wvt, *p_wrr, *p_bp, *p_wqk, *p_c2;
    cudaGetSymbolAddress((void**)&p_win,  sc_win);
    cudaGetSymbolAddress((void**)&p_wint, sc_wint);
    cudaGetSymbolAddress((void**)&p_map,  sc_map);
    cudaGetSymbolAddress((void**)&p_ft,   sc_ft);
    cudaGetSymbolAddress((void**)&p_p,    sc_p);
    cudaGetSymbolAddress((void**)&p_wvt,  sc_wvt);
    cudaGetSymbolAddress((void**)&p_wrr,  sc_wrr);
    cudaGetSymbolAddress((void**)&p_bp,   sc_bp);
    cudaGetSymbolAddress((void**)&p_wqk,  sc_wqk);
    cudaGetSymbolAddress((void**)&p_c2,   sc_c2);

    cudaFuncSetAttribute(gemm_cp_kernel<0>,
                         cudaFuncAttributeMaxDynamicSharedMemorySize, GEMM_SMEM);
    cudaFuncSetAttribute(gemm_cp_kernel<2>,
                         cudaFuncAttributeMaxDynamicSharedMemorySize, GEMM_SMEM);
    cudaFuncSetAttribute(gemm_cp_kernel<3>,
                         cudaFuncAttributeMaxDynamicSharedMemorySize, GEMM_SMEM);
    cudaFuncSetAttribute(attn_kernel,
                         cudaFuncAttributeMaxDynamicSharedMemorySize, ATTN_SMEM);

    // 0) weight prep: [wq;wk] packed, wr rounded, wv transposed; c2 = wr@bv + br
    prep_weights_kernel<<<1024, 256>>>(wq, wk, wv, wr, p_wqk, p_wvt, p_wrr);
    c2_kernel<<<1024, 128>>>(wr, bv, br, p_c2);

    // 1) Bp = wr @ wv  (combined channel weight; stored tf32 + k-permuted)
    gemm_cp_kernel<3><<<dim3(8, 8), 256, GEMM_SMEM>>>(
        p_wrr, p_wvt, nullptr, nullptr, p_bp, nullptr, nullptr);

    // 2) LayerNorm + window partition (fp32 residual + tf32-permuted GEMM copy)
    ln_win_kernel<<<NTOK, 256>>>(x, nw, nb, p_win, p_wint);

    // 3) fused Q/K projection: [seg_map | seg_ft] = win @ [wq;wk]^T + [bq;bk]
    gemm_cp_kernel<2><<<dim3(3, 392), 256, GEMM_SMEM>>>(
        p_wint, p_wqk, bq, bk, p_map, sem_out, p_ft);

    // 4) P = win @ Bp^T + c2   (replaces BOTH V-proj and R-proj GEMMs)
    gemm_cp_kernel<0><<<dim3(8, 392), 256, GEMM_SMEM>>>(
        p_wint, p_bp, p_c2, nullptr, p_p, nullptr, nullptr);

    // 5) attention (MMA S@P) + fused gamma/residual/window-reverse -> x_out
    attn_kernel<<<NWIN, 256, ATTN_SMEM>>>(p_map, p_ft, p_p, p_win, x_out, gamma);
}